// round 11
// baseline (speedup 1.0000x reference)
#include <cuda_runtime.h>
#include <cstdint>

#define B_   64
#define T_   1024
#define H_   512
#define I_   64
#define O_   8
#define ALPHA 0.2f
#define NSTD  0.05f

#define CL    4                 // cluster size (column tiles)
#define GRID  128               // 32 clusters x 4 CTAs, single wave
#define TPB   512
#define NB    2                 // batches per cluster
#define NC    128               // columns per CTA
#define NREG  44                // weight pairs kept in registers
#define EXPBYTES 4096           // full h (512 cols x 2 batches x 4B)
#define MBCOUNT 65              // 64 x-stager arrivals + 1 expect_tx arrival

// operand buffer (floats): per-ksub padded regions, (q,b,half) interleave
//   h  (k,b): (k>>7)*260 + ((k&127)>>1)*4 + b*2 + (k&1)   regions 0..1039
//   x  (i,b): XOFF + (i>>4)*36 + ((i&15)>>1)*4 + b*2 + (i&1)
#define KSTR  260               // ksub region stride (256 + 4 pad) floats
#define XOFF  1040              // 4*260
#define XSTR  36                // x ksub region stride (32 + 4 pad)
#define OPF   1184              // floats per buffer (1040 + 144)

// dynamic smem layout (bytes)
#define OFF_OP   0                          // float [2][OPF] = 9472
#define OFF_MBAR 9472                       // u64 [2]
#define OFF_SW   9488                       // u64 [28][TPB] = 114688
#define SMEM_TOTAL (OFF_SW + 28 * TPB * 8)  // 124176

// ---- packed f32x2 helpers (sm_100+) ----
__device__ __forceinline__ unsigned long long pk2(float lo, float hi) {
    unsigned long long v;
    asm("mov.b64 %0, {%1,%2};" : "=l"(v) : "f"(lo), "f"(hi));
    return v;
}
__device__ __forceinline__ void ffma2(unsigned long long& d,
                                      unsigned long long a,
                                      unsigned long long b) {
    asm("fma.rn.f32x2 %0, %1, %2, %0;" : "+l"(d) : "l"(a), "l"(b));
}
__device__ __forceinline__ float lo32(unsigned long long v) {
    return __uint_as_float((unsigned)(v & 0xffffffffu));
}
__device__ __forceinline__ float hi32(unsigned long long v) {
    return __uint_as_float((unsigned)(v >> 32));
}
__device__ __forceinline__ uint32_t smem_u32(const void* p) {
    uint32_t a;
    asm("{ .reg .u64 t; cvta.to.shared.u64 t, %1; cvt.u32.u64 %0, t; }"
        : "=r"(a) : "l"(p));
    return a;
}
__device__ __forceinline__ uint32_t mapa_rank(uint32_t laddr, uint32_t rank) {
    uint32_t ra;
    asm("mapa.shared::cluster.u32 %0, %1, %2;" : "=r"(ra) : "r"(laddr), "r"(rank));
    return ra;
}
__device__ __forceinline__ void st_async_b64(uint32_t raddr, unsigned long long v,
                                             uint32_t rmbar) {
    asm volatile(
        "st.async.shared::cluster.mbarrier::complete_tx::bytes.b64 [%0], %1, [%2];"
        :: "r"(raddr), "l"(v), "r"(rmbar) : "memory");
}
__device__ __forceinline__ void mbar_init(uint32_t mbar, uint32_t cnt) {
    asm volatile("mbarrier.init.shared.b64 [%0], %1;" :: "r"(mbar), "r"(cnt) : "memory");
}
__device__ __forceinline__ void mbar_expect_tx(uint32_t mbar, uint32_t bytes) {
    asm volatile("mbarrier.arrive.expect_tx.shared.b64 _, [%0], %1;"
                 :: "r"(mbar), "r"(bytes) : "memory");
}
__device__ __forceinline__ void mbar_arrive(uint32_t mbar) {
    asm volatile("mbarrier.arrive.release.cta.shared.b64 _, [%0];"
                 :: "r"(mbar) : "memory");
}
__device__ __forceinline__ void mbar_wait(uint32_t mbar, uint32_t parity) {
    uint32_t done;
    asm volatile(
        "{ .reg .pred P;\n"
        "  mbarrier.try_wait.parity.acquire.cta.shared::cta.b64 P, [%1], %2;\n"
        "  selp.b32 %0, 1, 0, P; }"
        : "=r"(done) : "r"(mbar), "r"(parity) : "memory");
    if (!done) {
        asm volatile(
            "{ .reg .pred P;\n"
            "WL%=:\n"
            "  mbarrier.try_wait.parity.acquire.cta.shared::cta.b64 P, [%0], %1, 0x989680;\n"
            "  @P bra WD%=;\n"
            "  bra WL%=;\n"
            "WD%=: }"
            :: "r"(mbar), "r"(parity) : "memory");
    }
}
__device__ __forceinline__ void cluster_sync() {
    asm volatile("barrier.cluster.arrive.aligned;" ::: "memory");
    asm volatile("barrier.cluster.wait.aligned;" ::: "memory");
}

// profiling alignment: capture lands on launch index 3 (0-based)
extern "C" __global__ void knop() {}

extern "C" __global__ void __launch_bounds__(TPB, 1) __cluster_dims__(CL, 1, 1)
rnn_main(const float* __restrict__ input, const float* __restrict__ noise,
         const float* __restrict__ wi, const float* __restrict__ si,
         const float* __restrict__ wrec, const float* __restrict__ bias,
         const float* __restrict__ wi_mask, const float* __restrict__ wrec_mask,
         const float* __restrict__ h0, float* __restrict__ traj)
{
    extern __shared__ __align__(16) char smem[];
    float* s_op = (float*)(smem + OFF_OP);                      // [2][OPF]
    unsigned long long* s_w = (unsigned long long*)(smem + OFF_SW); // [28][TPB]

    const int tid  = threadIdx.x;
    const int rank = blockIdx.x % CL;
    const int bg   = blockIdx.x / CL;
    const int C0   = rank * NC;
    const int B0   = bg * NB;

    // lane mapping: warp owns 8 cols; lane = (c_local&7)*4 + ksub
    const int warp = tid >> 5;
    const int lane = tid & 31;
    const int ksub = lane & 3;            // k-slice [0,4)
    const int cl8  = lane >> 2;           // col within warp [0,8)
    const int cc   = C0 + warp * 8 + cl8; // my global column
    const int kb   = ksub * 128;          // wrec k start
    const int ib   = ksub * 16;           // wi i start
    const bool fin  = (ksub == 0);        // finalize lane (holds col sums)
    const bool send = ((lane & 7) == 0);  // even-col finalize lane (sender)

    // -------- weights: 44 pairs in regs, 20 wrec + 8 wi pairs in smem -------
    unsigned long long wreg[NREG];        // 88 registers
#pragma unroll
    for (int pp = 0; pp < NREG; pp++) {
        int k0 = kb + 2 * pp;
        float a = fabsf(wrec[(size_t)k0 * H_ + cc]) * wrec_mask[(size_t)k0 * H_ + cc];
        float b = fabsf(wrec[(size_t)(k0 + 1) * H_ + cc]) * wrec_mask[(size_t)(k0 + 1) * H_ + cc];
        wreg[pp] = pk2(a, b);
    }
    for (int j = 0; j < 20; j++) {
        int k0 = kb + 2 * (NREG + j);
        float a = fabsf(wrec[(size_t)k0 * H_ + cc]) * wrec_mask[(size_t)k0 * H_ + cc];
        float b = fabsf(wrec[(size_t)(k0 + 1) * H_ + cc]) * wrec_mask[(size_t)(k0 + 1) * H_ + cc];
        s_w[j * TPB + tid] = pk2(a, b);
    }
    for (int j = 0; j < 8; j++) {
        int i0 = ib + 2 * j;
        float a = wi[(size_t)i0 * H_ + cc] * si[i0] * wi_mask[(size_t)i0 * H_ + cc];
        float b = wi[(size_t)(i0 + 1) * H_ + cc] * si[i0 + 1] * wi_mask[(size_t)(i0 + 1) * H_ + cc];
        s_w[(20 + j) * TPB + tid] = pk2(a, b);
    }

    const uint32_t s_op_u32 = smem_u32(s_op);
    const uint32_t mbar_u32 = smem_u32(smem + OFF_MBAR);
    // send destination byte offset for my column pair (sender lanes, cc even)
    const uint32_t dst_off = (uint32_t)(((cc >> 7) * KSTR + ((cc & 127) >> 1) * 4) * 4);

    const float fbias = bias[cc];

    // per-batch pointers for finalize lanes (col cc, batches B0, B0+1)
    const float* nz_p0 = noise + ((size_t)B0 * T_) * H_ + cc;           // += H_
    const float* nz_p1 = nz_p0 + (size_t)T_ * H_;
    float* tr_p0 = traj + ((size_t)B0 * (T_ + 1)) * H_ + cc;            // += H_
    float* tr_p1 = tr_p0 + (size_t)(T_ + 1) * H_;

    // x-stager role (tid < 64): batch xb, i-pair xi
    const int xb = tid >> 5, xi = (tid & 31) * 2;
    const float* x_p = input + ((size_t)(B0 + xb) * T_) * I_ + xi;      // += I_
    const uint32_t xslot = (uint32_t)(XOFF + (xi >> 4) * XSTR + ((xi & 15) >> 1) * 4 + xb * 2);

    // -------- init ----------------------------------------------------------
    if (tid == 0) {
        mbar_init(mbar_u32, MBCOUNT);
        mbar_init(mbar_u32 + 8, MBCOUNT);
    }
    float h_prev0 = h0[cc], h_prev1 = h_prev0;   // h0 broadcast over batch
    if (send) {
        float2 h0v = make_float2(h0[cc], h0[cc + 1]);
        *(float2*)tr_p0 = h0v;
        *(float2*)tr_p1 = h0v;
    }
    tr_p0 += H_; tr_p1 += H_;
    // stage relu(h0) into buffer 0
#pragma unroll
    for (int q = 0; q < 2; q++) {
        int e = tid * 2 + q;              // [0,1024): k = e>>1, b = e&1
        int k = e >> 1, b = e & 1;
        s_op[(k >> 7) * KSTR + ((k & 127) >> 1) * 4 + b * 2 + (k & 1)] = fmaxf(h0[k], 0.f);
    }
    if (tid < 64) {                       // stage x_0
        float2 xv = *(const float2*)x_p;
        *(float2*)&s_op[xslot] = xv;
    }
    __syncthreads();
    cluster_sync();   // mbarriers + buffer0 + smem weights visible

    int p = 0;
    uint32_t ph0 = 0, ph1 = 0;
    const float* x_pp = x_p + I_;         // next-step x pointer (stagers)
    for (int t = 0; t < T_; t++) {
        const int pn = p ^ 1;

        // ---- prefetch (before wait; consumed after matmul) ------------------
        float nz0 = 0.f, nz1 = 0.f;
        if (fin) { nz0 = *nz_p0; nz1 = *nz_p1; nz_p0 += H_; nz_p1 += H_; }
        float2 xnext = make_float2(0.f, 0.f);
        if (tid < 64 && t + 1 < T_) { xnext = *(const float2*)x_pp; x_pp += I_; }

        if (tid == 0 && t + 1 < T_)
            mbar_expect_tx(mbar_u32 + 8u * pn, EXPBYTES);

        // ---- per-warp wait on this step's buffer ----------------------------
        if (t > 0) {
            if (p == 0) { mbar_wait(mbar_u32, ph0);     ph0 ^= 1; }
            else        { mbar_wait(mbar_u32 + 8, ph1); ph1 ^= 1; }
        }

        // ---- matmul: 72 k-pairs x 2 batches, 1 column -----------------------
        const float* ob  = s_op + p * OPF + ksub * KSTR;
        const float* obx = s_op + p * OPF + XOFF + ksub * XSTR;
        const unsigned long long* swp = s_w + tid;

        unsigned long long a0 = 0ULL, a1 = 0ULL;
#pragma unroll
        for (int pp = 0; pp < NREG; pp++) {
            ulonglong2 v = *(const ulonglong2*)&ob[pp << 2];
            ffma2(a0, v.x, wreg[pp]);
            ffma2(a1, v.y, wreg[pp]);
        }
#pragma unroll
        for (int j = 0; j < 20; j++) {
            unsigned long long w = swp[j * TPB];
            ulonglong2 v = *(const ulonglong2*)&ob[(NREG + j) << 2];
            ffma2(a0, v.x, w);
            ffma2(a1, v.y, w);
        }
#pragma unroll
        for (int j = 0; j < 8; j++) {
            unsigned long long w = swp[(20 + j) * TPB];
            ulonglong2 v = *(const ulonglong2*)&obx[j << 2];
            ffma2(a0, v.x, w);
            ffma2(a1, v.y, w);
        }

        // ---- intra-warp k reduction: collapse + 2x bfly over ksub bits ------
        float s0 = lo32(a0) + hi32(a0);
        float s1 = lo32(a1) + hi32(a1);
        s0 += __shfl_xor_sync(0xffffffffu, s0, 1);
        s0 += __shfl_xor_sync(0xffffffffu, s0, 2);
        s1 += __shfl_xor_sync(0xffffffffu, s1, 1);
        s1 += __shfl_xor_sync(0xffffffffu, s1, 2);

        // ---- finalize in-warp: h update, pair up, send, traj ----------------
        float h_new0 = h_prev0 + NSTD * nz0 + ALPHA * (-h_prev0 + s0 + fbias);
        float h_new1 = h_prev1 + NSTD * nz1 + ALPHA * (-h_prev1 + s1 + fbias);
        float rv0 = fmaxf(h_new0, 0.f), rv1 = fmaxf(h_new1, 0.f);
        float nrv0 = __shfl_down_sync(0xffffffffu, rv0, 4);
        float nrv1 = __shfl_down_sync(0xffffffffu, rv1, 4);
        float nhn0 = __shfl_down_sync(0xffffffffu, h_new0, 4);
        float nhn1 = __shfl_down_sync(0xffffffffu, h_new1, 4);

        if (send) {
            if (t + 1 < T_) {
                unsigned long long m0 = pk2(rv0, nrv0);   // b0 pair (cc, cc+1)
                unsigned long long m1 = pk2(rv1, nrv1);   // b1 pair
                uint32_t doff = (uint32_t)pn * (OPF * 4) + dst_off;
                uint32_t moff = 8u * (uint32_t)pn;
#pragma unroll
                for (int r = 0; r < CL; r++) {
                    uint32_t ra = mapa_rank(s_op_u32, (uint32_t)r) + doff;
                    uint32_t rm = mapa_rank(mbar_u32, (uint32_t)r) + moff;
                    st_async_b64(ra,     m0, rm);
                    st_async_b64(ra + 8, m1, rm);
                }
            }
            *(float2*)tr_p0 = make_float2(h_new0, nhn0);
            *(float2*)tr_p1 = make_float2(h_new1, nhn1);
        }
        tr_p0 += H_; tr_p1 += H_;
        h_prev0 = h_new0;
        h_prev1 = h_new1;

        // ---- x staging for next buffer + arrival ----------------------------
        if (tid < 64 && t + 1 < T_) {
            *(float2*)&s_op[pn * OPF + xslot] = xnext;
            mbar_arrive(mbar_u32 + 8u * pn);
        }

        p = pn;
    }

    cluster_sync();   // no CTA exits while peers' st.async may target it
}

// output pass: out[b,t,o] = relu(traj[b,t+1,:]) @ wo_eff
extern "C" __global__ void __launch_bounds__(256)
rnn_out(const float* __restrict__ traj, const float* __restrict__ wo,
        const float* __restrict__ so, const float* __restrict__ wo_mask,
        float* __restrict__ out)
{
    __shared__ float s_wo[O_][H_];
    const int tid = threadIdx.x;
    for (int i = tid; i < H_ * O_; i += 256) {
        int c = i / O_, o = i % O_;
        s_wo[o][c] = wo[i] * so[o] * wo_mask[i];
    }
    __syncthreads();

    const int warp = tid >> 5, lane = tid & 31;
    const size_t row = (size_t)blockIdx.x * 8 + warp;   // b*T + t
    const int b = (int)(row >> 10);
    const int t = (int)(row & 1023);
    const float* tp = traj + ((size_t)b * (T_ + 1) + t + 1) * H_;

    float acc[O_];
#pragma unroll
    for (int o = 0; o < O_; o++) acc[o] = 0.f;

    for (int ccb = 0; ccb < H_; ccb += 32) {
        float r = fmaxf(tp[ccb + lane], 0.f);
#pragma unroll
        for (int o = 0; o < O_; o++) acc[o] += r * s_wo[o][ccb + lane];
    }
#pragma unroll
    for (int off = 16; off; off >>= 1)
#pragma unroll
        for (int o = 0; o < O_; o++)
            acc[o] += __shfl_down_sync(0xffffffffu, acc[o], off);
    if (lane == 0) {
#pragma unroll
        for (int o = 0; o < O_; o++) out[row * O_ + o] = acc[o];
    }
}

extern "C" void kernel_launch(void* const* d_in, const int* in_sizes, int n_in,
                              void* d_out, int out_size)
{
    (void)in_sizes; (void)n_in; (void)out_size;
    const float* input = (const float*)d_in[0];
    const float* noise = (const float*)d_in[1];
    const float* wi    = (const float*)d_in[2];
    const float* si    = (const float*)d_in[3];
    const float* wrec  = (const float*)d_in[4];
    const float* bias  = (const float*)d_in[5];
    const float* wo    = (const float*)d_in[6];
    const float* so    = (const float*)d_in[7];
    const float* wim   = (const float*)d_in[8];
    const float* wrm   = (const float*)d_in[9];
    const float* wom   = (const float*)d_in[10];
    const float* h0    = (const float*)d_in[11];

    float* out  = (float*)d_out;
    float* traj = out + (size_t)B_ * T_ * O_;   // [B, T+1, H] after [B, T, O]

    cudaFuncSetAttribute(rnn_main,
                         cudaFuncAttributeMaxDynamicSharedMemorySize, SMEM_TOTAL);

    // 3 no-op launches: aim ncu capture (launch idx 3) at rnn_main
    for (int i = 0; i < 3; i++) knop<<<1, 32>>>();

    rnn_main<<<GRID, TPB, SMEM_TOTAL>>>(input, noise, wi, si, wrec, bias,
                                        wim, wrm, h0, traj);
    rnn_out<<<(B_ * T_) / 8, 256>>>(traj, wo, so, wom, out);
}

// round 12
// speedup vs baseline: 1.5712x; 1.5712x over previous
#include <cuda_runtime.h>
#include <cstdint>

#define B_   64
#define T_   1024
#define H_   512
#define I_   64
#define O_   8
#define ALPHA 0.2f
#define NSTD  0.05f

#define CL    4                 // cluster size (column tiles)
#define GRID  128               // 32 clusters x 4 CTAs, single wave
#define TPB   512
#define NB    2                 // batches per cluster
#define NC    128               // columns per CTA
#define KS    4                 // k-slices (tid>>7, warp-uniform)
#define NREG  44                // weight pairs kept in registers
#define EXPBYTES 3072           // 3 remote 1KB blocks per buffer per step
#define MBCOUNT 65              // 64 x-stager arrivals + 1 expect_tx arrival

// operand buffer geometry (floats), 2-batch interleave by k-pair:
//   h element (k,b) -> (k>>1)*4 + b*2 + (k&1)        [0, 1024)
//   x element (i,b) -> 1024 + (i>>1)*4 + b*2 + (i&1) [1024, 1152)
#define OPF   1152
#define XBASE 1024

// dynamic smem layout (bytes)
#define OFF_OP   0              // float [2][OPF]           = 9216
#define OFF_RED  9216           // float [2][NB][KS][NC]    = 8192
#define OFF_MBAR 17408          // u64 [2]                  = 16
#define OFF_SW   17536          // u64 [28][TPB]            = 114688
#define SMEM_TOTAL (OFF_SW + 28 * TPB * 8)

// ---- packed f32x2 helpers (sm_100+) ----
__device__ __forceinline__ unsigned long long pk2(float lo, float hi) {
    unsigned long long v;
    asm("mov.b64 %0, {%1,%2};" : "=l"(v) : "f"(lo), "f"(hi));
    return v;
}
__device__ __forceinline__ void ffma2(unsigned long long& d,
                                      unsigned long long a,
                                      unsigned long long b) {
    asm("fma.rn.f32x2 %0, %1, %2, %0;" : "+l"(d) : "l"(a), "l"(b));
}
__device__ __forceinline__ float lo32(unsigned long long v) {
    return __uint_as_float((unsigned)(v & 0xffffffffu));
}
__device__ __forceinline__ float hi32(unsigned long long v) {
    return __uint_as_float((unsigned)(v >> 32));
}
__device__ __forceinline__ uint32_t smem_u32(const void* p) {
    uint32_t a;
    asm("{ .reg .u64 t; cvta.to.shared.u64 t, %1; cvt.u32.u64 %0, t; }"
        : "=r"(a) : "l"(p));
    return a;
}
__device__ __forceinline__ uint32_t mapa_rank(uint32_t laddr, uint32_t rank) {
    uint32_t ra;
    asm("mapa.shared::cluster.u32 %0, %1, %2;" : "=r"(ra) : "r"(laddr), "r"(rank));
    return ra;
}
// bulk smem->remote-smem copy with complete_tx on the remote mbarrier
__device__ __forceinline__ void bulk_copy_cluster(uint32_t dst, uint32_t src,
                                                  uint32_t bytes, uint32_t rmbar) {
    asm volatile(
        "cp.async.bulk.shared::cluster.shared::cta.mbarrier::complete_tx::bytes "
        "[%0], [%1], %2, [%3];"
        :: "r"(dst), "r"(src), "r"(bytes), "r"(rmbar) : "memory");
}
__device__ __forceinline__ void fence_proxy_async_cta() {
    asm volatile("fence.proxy.async.shared::cta;" ::: "memory");
}
__device__ __forceinline__ void mbar_init(uint32_t mbar, uint32_t cnt) {
    asm volatile("mbarrier.init.shared.b64 [%0], %1;" :: "r"(mbar), "r"(cnt) : "memory");
}
__device__ __forceinline__ void mbar_expect_tx(uint32_t mbar, uint32_t bytes) {
    asm volatile("mbarrier.arrive.expect_tx.shared.b64 _, [%0], %1;"
                 :: "r"(mbar), "r"(bytes) : "memory");
}
__device__ __forceinline__ void mbar_arrive(uint32_t mbar) {
    asm volatile("mbarrier.arrive.release.cta.shared.b64 _, [%0];"
                 :: "r"(mbar) : "memory");
}
__device__ __forceinline__ void mbar_wait(uint32_t mbar, uint32_t parity) {
    uint32_t done;
    asm volatile(
        "{ .reg .pred P;\n"
        "  mbarrier.try_wait.parity.acquire.cta.shared::cta.b64 P, [%1], %2;\n"
        "  selp.b32 %0, 1, 0, P; }"
        : "=r"(done) : "r"(mbar), "r"(parity) : "memory");
    if (!done) {
        asm volatile(
            "{ .reg .pred P;\n"
            "WL%=:\n"
            "  mbarrier.try_wait.parity.acquire.cta.shared::cta.b64 P, [%0], %1, 0x989680;\n"
            "  @P bra WD%=;\n"
            "  bra WL%=;\n"
            "WD%=: }"
            :: "r"(mbar), "r"(parity) : "memory");
    }
}
__device__ __forceinline__ void cluster_sync() {
    asm volatile("barrier.cluster.arrive.aligned;" ::: "memory");
    asm volatile("barrier.cluster.wait.aligned;" ::: "memory");
}

// profiling alignment: capture lands on launch index 3 (0-based)
extern "C" __global__ void knop() {}

extern "C" __global__ void __launch_bounds__(TPB, 1) __cluster_dims__(CL, 1, 1)
rnn_main(const float* __restrict__ input, const float* __restrict__ noise,
         const float* __restrict__ wi, const float* __restrict__ si,
         const float* __restrict__ wrec, const float* __restrict__ bias,
         const float* __restrict__ wi_mask, const float* __restrict__ wrec_mask,
         const float* __restrict__ h0, float* __restrict__ traj)
{
    extern __shared__ __align__(16) char smem[];
    float* s_op  = (float*)(smem + OFF_OP);             // [2][OPF]
    float* s_rd  = (float*)(smem + OFF_RED);            // [2][NB][KS][NC]
    unsigned long long* s_w = (unsigned long long*)(smem + OFF_SW); // [28][TPB]

    const int tid  = threadIdx.x;
    const int rank = blockIdx.x % CL;
    const int bg   = blockIdx.x / CL;
    const int C0   = rank * NC;
    const int B0   = bg * NB;

    // compute-role: 128 column-threads x 4 k-slices (warp-uniform ksub)
    const int ct   = tid & 127;
    const int ksub = tid >> 7;
    const int cc   = C0 + ct;
    const int kb   = ksub * (H_ / KS);    // 128 wrec k start
    const int ib   = ksub * (I_ / KS);    // 16 wi k start

    // finalize-role (tid < 256): batch fb, column fc
    const int fb = tid >> 7;
    const int fc = tid & 127;
    const int gb = B0 + fb;
    const int gc = C0 + fc;

    // -------- weights: 44 pairs in regs, 28 pairs in smem -------------------
    unsigned long long wreg[NREG];        // 88 registers
#pragma unroll
    for (int pp = 0; pp < NREG; pp++) {
        int k0 = kb + 2 * pp;
        float a = fabsf(wrec[(size_t)k0 * H_ + cc]) * wrec_mask[(size_t)k0 * H_ + cc];
        float b = fabsf(wrec[(size_t)(k0 + 1) * H_ + cc]) * wrec_mask[(size_t)(k0 + 1) * H_ + cc];
        wreg[pp] = pk2(a, b);
    }
    for (int j = 0; j < 20; j++) {        // wrec pairs 44..63
        int k0 = kb + 2 * (NREG + j);
        float a = fabsf(wrec[(size_t)k0 * H_ + cc]) * wrec_mask[(size_t)k0 * H_ + cc];
        float b = fabsf(wrec[(size_t)(k0 + 1) * H_ + cc]) * wrec_mask[(size_t)(k0 + 1) * H_ + cc];
        s_w[j * TPB + tid] = pk2(a, b);
    }
    for (int j = 0; j < 8; j++) {         // wi pairs 0..7
        int i0 = ib + 2 * j;
        float a = wi[(size_t)i0 * H_ + cc] * si[i0] * wi_mask[(size_t)i0 * H_ + cc];
        float b = wi[(size_t)(i0 + 1) * H_ + cc] * si[i0 + 1] * wi_mask[(size_t)(i0 + 1) * H_ + cc];
        s_w[(20 + j) * TPB + tid] = pk2(a, b);
    }

    const uint32_t s_op_u32 = smem_u32(s_op);
    const uint32_t mbar_u32 = smem_u32(smem + OFF_MBAR);
    // my own-slot float index within the h region (finalize threads)
    const int own_slot = (gc >> 1) * 4 + fb * 2 + (gc & 1);
    // my CTA's contiguous 1KB block byte offset within a buffer's h region
    const uint32_t blk_off = (uint32_t)(C0 * 8);

    const float fbias = (tid < 256) ? bias[gc] : 0.f;

    // the peer rank this sender thread (tid<3) services
    const int peer = (tid < 3) ? (tid >= rank ? tid + 1 : tid) : 0;

    // incremented pointers
    const float* nz_p = noise + ((size_t)gb * T_) * H_ + gc;            // += H_
    const int xb = (tid >> 5) & 1, xi = (tid & 31) * 2;                 // tid 256..319
    const float* x_p  = input + ((size_t)(B0 + xb) * T_) * I_ + xi;     // += I_
    float*       tr_p = traj + ((size_t)gb * (T_ + 1)) * H_ + gc;       // += H_

    // -------- init ----------------------------------------------------------
    if (tid == 0) {
        mbar_init(mbar_u32, MBCOUNT);
        mbar_init(mbar_u32 + 8, MBCOUNT);
    }
    float h_prev = 0.f;
    if (tid < 256) {
        h_prev = h0[gc];
        *tr_p = h_prev;
        tr_p += H_;
    }
    // stage relu(h0) into buffer 0 (element e encodes (pair,b,half) directly)
#pragma unroll
    for (int q = 0; q < 2; q++) {
        int e = tid * 2 + q;              // [0,1024)
        int k = (e >> 2) * 2 + (e & 1);
        s_op[e] = fmaxf(h0[k], 0.f);
    }
    if (tid >= 256 && tid < 320) {        // stage x_0
        float2 xv = *(const float2*)x_p;
        *(float2*)&s_op[XBASE + (xi >> 1) * 4 + xb * 2] = xv;
        x_p += I_;
    }
    __syncthreads();
    cluster_sync();   // mbarriers + buffer0 + smem weights visible

    int p = 0;
    uint32_t ph0 = 0, ph1 = 0;
    for (int t = 0; t < T_; t++) {
        const int pn = p ^ 1;

        // ---- prefetch -------------------------------------------------------
        float nz = 0.f;
        if (tid < 256) { nz = *nz_p; nz_p += H_; }
        float2 xnext = make_float2(0.f, 0.f);
        if (tid >= 256 && tid < 320 && t + 1 < T_) {
            xnext = *(const float2*)x_p; x_p += I_;
        }

        if (tid == 0 && t + 1 < T_)
            mbar_expect_tx(mbar_u32 + 8u * pn, EXPBYTES);

        // ---- wait for this step's operands (h blocks + x staged) -----------
        if (t > 0) {
            if (p == 0) { mbar_wait(mbar_u32, ph0);     ph0 ^= 1; }
            else        { mbar_wait(mbar_u32 + 8, ph1); ph1 ^= 1; }
        }

        // ---- matmul: 72 k-pairs x 2 batches, 1 column ----------------------
        const float* ob  = s_op + p * OPF + (ksub << 8);      // wrec operands
        const float* obx = s_op + p * OPF + XBASE + (ksub << 5); // wi operands
        const unsigned long long* swp = s_w + tid;

        unsigned long long a0 = 0ULL, a1 = 0ULL;
#pragma unroll
        for (int pp = 0; pp < NREG; pp++) {
            ulonglong2 v = *(const ulonglong2*)&ob[pp << 2];
            ffma2(a0, v.x, wreg[pp]);
            ffma2(a1, v.y, wreg[pp]);
        }
#pragma unroll
        for (int j = 0; j < 20; j++) {
            unsigned long long w = swp[j * TPB];
            ulonglong2 v = *(const ulonglong2*)&ob[(NREG + j) << 2];
            ffma2(a0, v.x, w);
            ffma2(a1, v.y, w);
        }
#pragma unroll
        for (int j = 0; j < 8; j++) {
            unsigned long long w = swp[(20 + j) * TPB];
            ulonglong2 v = *(const ulonglong2*)&obx[j << 2];
            ffma2(a0, v.x, w);
            ffma2(a1, v.y, w);
        }
        // collapse packed halves -> f32 partials (double-buffered by p)
        float* rd = s_rd + ((p * NB) * KS + ksub) * NC + ct;
        rd[0]       = lo32(a0) + hi32(a0);
        rd[KS * NC] = lo32(a1) + hi32(a1);

        // stage x_{t+1} + arrive on next buffer's barrier
        if (tid >= 256 && tid < 320 && t + 1 < T_) {
            *(float2*)&s_op[pn * OPF + XBASE + (xi >> 1) * 4 + xb * 2] = xnext;
            mbar_arrive(mbar_u32 + 8u * pn);
        }
        __syncthreads();                  // bar1: partials + x staging visible

        // ---- finalize: sum 4 slices, h update, local STS, traj -------------
        if (tid < 256) {
            const float* rb = s_rd + ((p * NB + fb) * KS) * NC + fc;
            float s = rb[0] + rb[NC] + rb[2 * NC] + rb[3 * NC];

            float h_new = h_prev + NSTD * nz + ALPHA * (-h_prev + s + fbias);
            // own block of next buffer: plain local store
            s_op[pn * OPF + own_slot] = fmaxf(h_new, 0.f);
            *tr_p = h_new;
            tr_p += H_;
            h_prev = h_new;
        }
        __syncthreads();                  // bar2: own h block complete

        // ---- 3 bulk copies (1KB each) of own block to the 3 peers ----------
        if (tid < 3 && t + 1 < T_) {
            fence_proxy_async_cta();
            uint32_t off = (uint32_t)pn * (OPF * 4) + blk_off;
            uint32_t src = s_op_u32 + off;
            uint32_t dst = mapa_rank(s_op_u32, (uint32_t)peer) + off;
            uint32_t rmb = mapa_rank(mbar_u32, (uint32_t)peer) + 8u * (uint32_t)pn;
            bulk_copy_cluster(dst, src, 1024u, rmb);
        }

        p = pn;
    }

    cluster_sync();   // no CTA exits while peers' copies may target it
}

// output pass: out[b,t,o] = relu(traj[b,t+1,:]) @ wo_eff
extern "C" __global__ void __launch_bounds__(256)
rnn_out(const float* __restrict__ traj, const float* __restrict__ wo,
        const float* __restrict__ so, const float* __restrict__ wo_mask,
        float* __restrict__ out)
{
    __shared__ float s_wo[O_][H_];
    const int tid = threadIdx.x;
    for (int i = tid; i < H_ * O_; i += 256) {
        int c = i / O_, o = i % O_;
        s_wo[o][c] = wo[i] * so[o] * wo_mask[i];
    }
    __syncthreads();

    const int warp = tid >> 5, lane = tid & 31;
    const size_t row = (size_t)blockIdx.x * 8 + warp;   // b*T + t
    const int b = (int)(row >> 10);
    const int t = (int)(row & 1023);
    const float* tp = traj + ((size_t)b * (T_ + 1) + t + 1) * H_;

    float acc[O_];
#pragma unroll
    for (int o = 0; o < O_; o++) acc[o] = 0.f;

    for (int ccb = 0; ccb < H_; ccb += 32) {
        float r = fmaxf(tp[ccb + lane], 0.f);
#pragma unroll
        for (int o = 0; o < O_; o++) acc[o] += r * s_wo[o][ccb + lane];
    }
#pragma unroll
    for (int off = 16; off; off >>= 1)
#pragma unroll
        for (int o = 0; o < O_; o++)
            acc[o] += __shfl_down_sync(0xffffffffu, acc[o], off);
    if (lane == 0) {
#pragma unroll
        for (int o = 0; o < O_; o++) out[row * O_ + o] = acc[o];
    }
}

extern "C" void kernel_launch(void* const* d_in, const int* in_sizes, int n_in,
                              void* d_out, int out_size)
{
    (void)in_sizes; (void)n_in; (void)out_size;
    const float* input = (const float*)d_in[0];
    const float* noise = (const float*)d_in[1];
    const float* wi    = (const float*)d_in[2];
    const float* si    = (const float*)d_in[3];
    const float* wrec  = (const float*)d_in[4];
    const float* bias  = (const float*)d_in[5];
    const float* wo    = (const float*)d_in[6];
    const float* so    = (const float*)d_in[7];
    const float* wim   = (const float*)d_in[8];
    const float* wrm   = (const float*)d_in[9];
    const float* wom   = (const float*)d_in[10];
    const float* h0    = (const float*)d_in[11];

    float* out  = (float*)d_out;
    float* traj = out + (size_t)B_ * T_ * O_;   // [B, T+1, H] after [B, T, O]

    cudaFuncSetAttribute(rnn_main,
                         cudaFuncAttributeMaxDynamicSharedMemorySize, SMEM_TOTAL);

    // 3 no-op launches: aim ncu capture (launch idx 3) at rnn_main
    for (int i = 0; i < 3; i++) knop<<<1, 32>>>();

    rnn_main<<<GRID, TPB, SMEM_TOTAL>>>(input, noise, wi, si, wrec, bias,
                                        wim, wrm, h0, traj);
    rnn_out<<<(B_ * T_) / 8, 256>>>(traj, wo, so, wom, out);
}

// round 13
// speedup vs baseline: 2.1211x; 1.3500x over previous
#include <cuda_runtime.h>
#include <cstdint>

#define B_   64
#define T_   1024
#define H_   512
#define I_   64
#define O_   8
#define ALPHA 0.2f
#define NSTD  0.05f

#define CL    4                 // cluster size (column tiles)
#define GRID  128               // 32 clusters x 4 CTAs, single wave
#define TPB   512
#define NB    2                 // batches per cluster
#define NC    128               // columns per CTA
#define KS    8                 // k-slices (tid>>6, warp-uniform)
#define NWREG 22                // weight pairs in registers per column
#define NSWJ  14                // weight pair-slots in smem (10 wrec + 4 wi)
#define EXPBYTES 3072           // 3 remote 1KB blocks per buffer per step
#define MBCOUNT 65              // 64 x-stager arrivals + 1 expect_tx arrival

// operand buffer geometry (floats), 2-batch interleave by k-pair:
//   h element (k,b) -> (k>>1)*4 + b*2 + (k&1)        [0, 1024)
//   x element (i,b) -> 1024 + (i>>1)*4 + b*2 + (i&1) [1024, 1152)
#define OPF   1152
#define XBASE 1024

// dynamic smem layout (bytes)
#define OFF_OP   0               // float [2][OPF]            = 9216
#define OFF_RED  9216            // float [2][NB][KS][NC]     = 16384
#define OFF_MBAR 25600           // u64 [2]                   = 16
#define OFF_SW   25728           // u64 [NSWJ][TPB][2]        = 114688
#define SMEM_TOTAL (OFF_SW + NSWJ * TPB * 16)

// ---- packed f32x2 helpers (sm_100+) ----
__device__ __forceinline__ unsigned long long pk2(float lo, float hi) {
    unsigned long long v;
    asm("mov.b64 %0, {%1,%2};" : "=l"(v) : "f"(lo), "f"(hi));
    return v;
}
__device__ __forceinline__ void ffma2(unsigned long long& d,
                                      unsigned long long a,
                                      unsigned long long b) {
    asm("fma.rn.f32x2 %0, %1, %2, %0;" : "+l"(d) : "l"(a), "l"(b));
}
__device__ __forceinline__ float lo32(unsigned long long v) {
    return __uint_as_float((unsigned)(v & 0xffffffffu));
}
__device__ __forceinline__ float hi32(unsigned long long v) {
    return __uint_as_float((unsigned)(v >> 32));
}
__device__ __forceinline__ uint32_t smem_u32(const void* p) {
    uint32_t a;
    asm("{ .reg .u64 t; cvta.to.shared.u64 t, %1; cvt.u32.u64 %0, t; }"
        : "=r"(a) : "l"(p));
    return a;
}
__device__ __forceinline__ uint32_t mapa_rank(uint32_t laddr, uint32_t rank) {
    uint32_t ra;
    asm("mapa.shared::cluster.u32 %0, %1, %2;" : "=r"(ra) : "r"(laddr), "r"(rank));
    return ra;
}
__device__ __forceinline__ void bulk_copy_cluster(uint32_t dst, uint32_t src,
                                                  uint32_t bytes, uint32_t rmbar) {
    asm volatile(
        "cp.async.bulk.shared::cluster.shared::cta.mbarrier::complete_tx::bytes "
        "[%0], [%1], %2, [%3];"
        :: "r"(dst), "r"(src), "r"(bytes), "r"(rmbar) : "memory");
}
__device__ __forceinline__ void fence_proxy_async_cta() {
    asm volatile("fence.proxy.async.shared::cta;" ::: "memory");
}
__device__ __forceinline__ void mbar_init(uint32_t mbar, uint32_t cnt) {
    asm volatile("mbarrier.init.shared.b64 [%0], %1;" :: "r"(mbar), "r"(cnt) : "memory");
}
__device__ __forceinline__ void mbar_expect_tx(uint32_t mbar, uint32_t bytes) {
    asm volatile("mbarrier.arrive.expect_tx.shared.b64 _, [%0], %1;"
                 :: "r"(mbar), "r"(bytes) : "memory");
}
__device__ __forceinline__ void mbar_arrive(uint32_t mbar) {
    asm volatile("mbarrier.arrive.release.cta.shared.b64 _, [%0];"
                 :: "r"(mbar) : "memory");
}
__device__ __forceinline__ void mbar_wait(uint32_t mbar, uint32_t parity) {
    uint32_t done;
    asm volatile(
        "{ .reg .pred P;\n"
        "  mbarrier.try_wait.parity.acquire.cta.shared::cta.b64 P, [%1], %2;\n"
        "  selp.b32 %0, 1, 0, P; }"
        : "=r"(done) : "r"(mbar), "r"(parity) : "memory");
    if (!done) {
        asm volatile(
            "{ .reg .pred P;\n"
            "WL%=:\n"
            "  mbarrier.try_wait.parity.acquire.cta.shared::cta.b64 P, [%0], %1, 0x989680;\n"
            "  @P bra WD%=;\n"
            "  bra WL%=;\n"
            "WD%=: }"
            :: "r"(mbar), "r"(parity) : "memory");
    }
}
__device__ __forceinline__ void cluster_sync() {
    asm volatile("barrier.cluster.arrive.aligned;" ::: "memory");
    asm volatile("barrier.cluster.wait.aligned;" ::: "memory");
}

// profiling alignment: capture lands on launch index 3 (0-based)
extern "C" __global__ void knop() {}

extern "C" __global__ void __launch_bounds__(TPB, 1) __cluster_dims__(CL, 1, 1)
rnn_main(const float* __restrict__ input, const float* __restrict__ noise,
         const float* __restrict__ wi, const float* __restrict__ si,
         const float* __restrict__ wrec, const float* __restrict__ bias,
         const float* __restrict__ wi_mask, const float* __restrict__ wrec_mask,
         const float* __restrict__ h0, float* __restrict__ traj)
{
    extern __shared__ __align__(16) char smem[];
    float* s_op  = (float*)(smem + OFF_OP);             // [2][OPF]
    float* s_rd  = (float*)(smem + OFF_RED);            // [2][NB][KS][NC]
    unsigned long long* s_w = (unsigned long long*)(smem + OFF_SW); // [NSWJ][TPB][2]

    const int tid  = threadIdx.x;
    const int rank = blockIdx.x % CL;
    const int bg   = blockIdx.x / CL;
    const int C0   = rank * NC;
    const int B0   = bg * NB;

    // compute-role: 64 column-threads (2 cols each) x 8 k-slices (warp-uniform)
    const int ct   = tid & 63;
    const int ksub = tid >> 6;
    const int c0   = C0 + ct * 2;
    const int c1   = c0 + 1;
    const int kb   = ksub * (H_ / KS);    // 64 wrec k start
    const int ib   = ksub * (I_ / KS);    // 8 wi k start

    // finalize-role (tid < 256): batch fb, column fc
    const int fb = tid >> 7;
    const int fc = tid & 127;
    const int gb = B0 + fb;
    const int gc = C0 + fc;

    // -------- weights: 22 reg pairs/col; 10 wrec + 4 wi pairs/col in smem ---
    unsigned long long wr0[NWREG], wr1[NWREG];   // 88 registers
#pragma unroll
    for (int pp = 0; pp < NWREG; pp++) {
        int k0 = kb + 2 * pp;
        float a0 = fabsf(wrec[(size_t)k0 * H_ + c0]) * wrec_mask[(size_t)k0 * H_ + c0];
        float a1 = fabsf(wrec[(size_t)(k0 + 1) * H_ + c0]) * wrec_mask[(size_t)(k0 + 1) * H_ + c0];
        float b0 = fabsf(wrec[(size_t)k0 * H_ + c1]) * wrec_mask[(size_t)k0 * H_ + c1];
        float b1 = fabsf(wrec[(size_t)(k0 + 1) * H_ + c1]) * wrec_mask[(size_t)(k0 + 1) * H_ + c1];
        wr0[pp] = pk2(a0, a1);
        wr1[pp] = pk2(b0, b1);
    }
    for (int j = 0; j < 10; j++) {        // wrec pairs 22..31, both cols
        int k0 = kb + 2 * (NWREG + j);
        float a0 = fabsf(wrec[(size_t)k0 * H_ + c0]) * wrec_mask[(size_t)k0 * H_ + c0];
        float a1 = fabsf(wrec[(size_t)(k0 + 1) * H_ + c0]) * wrec_mask[(size_t)(k0 + 1) * H_ + c0];
        float b0 = fabsf(wrec[(size_t)k0 * H_ + c1]) * wrec_mask[(size_t)k0 * H_ + c1];
        float b1 = fabsf(wrec[(size_t)(k0 + 1) * H_ + c1]) * wrec_mask[(size_t)(k0 + 1) * H_ + c1];
        s_w[(j * TPB + tid) * 2 + 0] = pk2(a0, a1);
        s_w[(j * TPB + tid) * 2 + 1] = pk2(b0, b1);
    }
    for (int j = 0; j < 4; j++) {         // wi pairs 0..3, both cols
        int i0 = ib + 2 * j;
        float a0 = wi[(size_t)i0 * H_ + c0] * si[i0] * wi_mask[(size_t)i0 * H_ + c0];
        float a1 = wi[(size_t)(i0 + 1) * H_ + c0] * si[i0 + 1] * wi_mask[(size_t)(i0 + 1) * H_ + c0];
        float b0 = wi[(size_t)i0 * H_ + c1] * si[i0] * wi_mask[(size_t)i0 * H_ + c1];
        float b1 = wi[(size_t)(i0 + 1) * H_ + c1] * si[i0 + 1] * wi_mask[(size_t)(i0 + 1) * H_ + c1];
        s_w[((10 + j) * TPB + tid) * 2 + 0] = pk2(a0, a1);
        s_w[((10 + j) * TPB + tid) * 2 + 1] = pk2(b0, b1);
    }

    const uint32_t s_op_u32 = smem_u32(s_op);
    const uint32_t mbar_u32 = smem_u32(smem + OFF_MBAR);
    // my own-slot float index within the h region (finalize threads)
    const int own_slot = (gc >> 1) * 4 + fb * 2 + (gc & 1);
    // my CTA's contiguous 1KB block byte offset within a buffer's h region
    const uint32_t blk_off = (uint32_t)(C0 * 8);

    const float fbias = (tid < 256) ? bias[gc] : 0.f;

    // the peer rank this sender thread (tid<3) services
    const int peer = (tid < 3) ? (tid >= rank ? tid + 1 : tid) : 0;

    // incremented pointers
    const float* nz_p = noise + ((size_t)gb * T_) * H_ + gc;            // += H_
    const int xb = (tid >> 5) & 1, xi = (tid & 31) * 2;                 // tid 256..319
    const float* x_p  = input + ((size_t)(B0 + xb) * T_) * I_ + xi;     // += I_
    float*       tr_p = traj + ((size_t)gb * (T_ + 1)) * H_ + gc;       // += H_

    // -------- init ----------------------------------------------------------
    if (tid == 0) {
        mbar_init(mbar_u32, MBCOUNT);
        mbar_init(mbar_u32 + 8, MBCOUNT);
    }
    float h_prev = 0.f;
    if (tid < 256) {
        h_prev = h0[gc];
        *tr_p = h_prev;
        tr_p += H_;
    }
    // stage relu(h0) into buffer 0 (element e encodes (pair,b,half) directly)
#pragma unroll
    for (int q = 0; q < 2; q++) {
        int e = tid * 2 + q;              // [0,1024)
        int k = (e >> 2) * 2 + (e & 1);
        s_op[e] = fmaxf(h0[k], 0.f);
    }
    if (tid >= 256 && tid < 320) {        // stage x_0
        float2 xv = *(const float2*)x_p;
        *(float2*)&s_op[XBASE + (xi >> 1) * 4 + xb * 2] = xv;
        x_p += I_;
    }
    __syncthreads();
    cluster_sync();   // mbarriers + buffer0 + smem weights visible

    int p = 0;
    uint32_t ph0 = 0, ph1 = 0;
    for (int t = 0; t < T_; t++) {
        const int pn = p ^ 1;

        // ---- prefetch -------------------------------------------------------
        float nz = 0.f;
        if (tid < 256) { nz = *nz_p; nz_p += H_; }
        float2 xnext = make_float2(0.f, 0.f);
        if (tid >= 256 && tid < 320 && t + 1 < T_) {
            xnext = *(const float2*)x_p; x_p += I_;
        }

        if (tid == 0 && t + 1 < T_)
            mbar_expect_tx(mbar_u32 + 8u * pn, EXPBYTES);

        // ---- wait for this step's operands (h blocks + x staged) -----------
        if (t > 0) {
            if (p == 0) { mbar_wait(mbar_u32, ph0);     ph0 ^= 1; }
            else        { mbar_wait(mbar_u32 + 8, ph1); ph1 ^= 1; }
        }

        // ---- matmul: 36 k-pairs x 2 batches x 2 cols ------------------------
        const float* ob  = s_op + p * OPF + (ksub << 7);         // wrec pairs
        const float* obx = s_op + p * OPF + XBASE + (ksub << 4); // wi pairs

        unsigned long long a00 = 0ULL, a01 = 0ULL, a10 = 0ULL, a11 = 0ULL;
#pragma unroll
        for (int pp = 0; pp < NWREG; pp++) {
            ulonglong2 v = *(const ulonglong2*)&ob[pp << 2];
            ffma2(a00, v.x, wr0[pp]);
            ffma2(a01, v.y, wr0[pp]);
            ffma2(a10, v.x, wr1[pp]);
            ffma2(a11, v.y, wr1[pp]);
        }
#pragma unroll
        for (int j = 0; j < 10; j++) {
            ulonglong2 w = *(const ulonglong2*)&s_w[(j * TPB + tid) * 2];
            ulonglong2 v = *(const ulonglong2*)&ob[(NWREG + j) << 2];
            ffma2(a00, v.x, w.x);
            ffma2(a01, v.y, w.x);
            ffma2(a10, v.x, w.y);
            ffma2(a11, v.y, w.y);
        }
#pragma unroll
        for (int j = 0; j < 4; j++) {
            ulonglong2 w = *(const ulonglong2*)&s_w[((10 + j) * TPB + tid) * 2];
            ulonglong2 v = *(const ulonglong2*)&obx[j << 2];
            ffma2(a00, v.x, w.x);
            ffma2(a01, v.y, w.x);
            ffma2(a10, v.x, w.y);
            ffma2(a11, v.y, w.y);
        }

        // collapse packed halves -> f32 partials (double-buffered by p)
        {
            float* rd0 = s_rd + ((p * NB + 0) * KS + ksub) * NC + ct * 2;
            float* rd1 = s_rd + ((p * NB + 1) * KS + ksub) * NC + ct * 2;
            *(float2*)rd0 = make_float2(lo32(a00) + hi32(a00),
                                        lo32(a10) + hi32(a10));
            *(float2*)rd1 = make_float2(lo32(a01) + hi32(a01),
                                        lo32(a11) + hi32(a11));
        }

        // stage x_{t+1} + arrive on next buffer's barrier
        if (tid >= 256 && tid < 320 && t + 1 < T_) {
            *(float2*)&s_op[pn * OPF + XBASE + (xi >> 1) * 4 + xb * 2] = xnext;
            mbar_arrive(mbar_u32 + 8u * pn);
        }
        __syncthreads();                  // bar1: partials + x staging visible

        // ---- finalize: sum 8 slices, h update, local STS, traj -------------
        if (tid < 256) {
            const float* rb = s_rd + ((p * NB + fb) * KS) * NC + fc;
            float s = ((rb[0] + rb[NC]) + (rb[2 * NC] + rb[3 * NC]))
                    + ((rb[4 * NC] + rb[5 * NC]) + (rb[6 * NC] + rb[7 * NC]));

            float h_new = h_prev + NSTD * nz + ALPHA * (-h_prev + s + fbias);
            // own block of next buffer: plain local store
            s_op[pn * OPF + own_slot] = fmaxf(h_new, 0.f);
            *tr_p = h_new;
            tr_p += H_;
            h_prev = h_new;
        }
        __syncthreads();                  // bar2: own h block complete

        // ---- 3 bulk copies (1KB each) of own block to the 3 peers ----------
        if (tid < 3 && t + 1 < T_) {
            fence_proxy_async_cta();
            uint32_t off = (uint32_t)pn * (OPF * 4) + blk_off;
            uint32_t src = s_op_u32 + off;
            uint32_t dst = mapa_rank(s_op_u32, (uint32_t)peer) + off;
            uint32_t rmb = mapa_rank(mbar_u32, (uint32_t)peer) + 8u * (uint32_t)pn;
            bulk_copy_cluster(dst, src, 1024u, rmb);
        }

        p = pn;
    }

    cluster_sync();   // no CTA exits while peers' copies may target it
}

// output pass: out[b,t,o] = relu(traj[b,t+1,:]) @ wo_eff
extern "C" __global__ void __launch_bounds__(256)
rnn_out(const float* __restrict__ traj, const float* __restrict__ wo,
        const float* __restrict__ so, const float* __restrict__ wo_mask,
        float* __restrict__ out)
{
    __shared__ float s_wo[O_][H_];
    const int tid = threadIdx.x;
    for (int i = tid; i < H_ * O_; i += 256) {
        int c = i / O_, o = i % O_;
        s_wo[o][c] = wo[i] * so[o] * wo_mask[i];
    }
    __syncthreads();

    const int warp = tid >> 5, lane = tid & 31;
    const size_t row = (size_t)blockIdx.x * 8 + warp;   // b*T + t
    const int b = (int)(row >> 10);
    const int t = (int)(row & 1023);
    const float* tp = traj + ((size_t)b * (T_ + 1) + t + 1) * H_;

    float acc[O_];
#pragma unroll
    for (int o = 0; o < O_; o++) acc[o] = 0.f;

    for (int ccb = 0; ccb < H_; ccb += 32) {
        float r = fmaxf(tp[ccb + lane], 0.f);
#pragma unroll
        for (int o = 0; o < O_; o++) acc[o] += r * s_wo[o][ccb + lane];
    }
#pragma unroll
    for (int off = 16; off; off >>= 1)
#pragma unroll
        for (int o = 0; o < O_; o++)
            acc[o] += __shfl_down_sync(0xffffffffu, acc[o], off);
    if (lane == 0) {
#pragma unroll
        for (int o = 0; o < O_; o++) out[row * O_ + o] = acc[o];
    }
}

extern "C" void kernel_launch(void* const* d_in, const int* in_sizes, int n_in,
                              void* d_out, int out_size)
{
    (void)in_sizes; (void)n_in; (void)out_size;
    const float* input = (const float*)d_in[0];
    const float* noise = (const float*)d_in[1];
    const float* wi    = (const float*)d_in[2];
    const float* si    = (const float*)d_in[3];
    const float* wrec  = (const float*)d_in[4];
    const float* bias  = (const float*)d_in[5];
    const float* wo    = (const float*)d_in[6];
    const float* so    = (const float*)d_in[7];
    const float* wim   = (const float*)d_in[8];
    const float* wrm   = (const float*)d_in[9];
    const float* wom   = (const float*)d_in[10];
    const float* h0    = (const float*)d_in[11];

    float* out  = (float*)d_out;
    float* traj = out + (size_t)B_ * T_ * O_;   // [B, T+1, H] after [B, T, O]

    cudaFuncSetAttribute(rnn_main,
                         cudaFuncAttributeMaxDynamicSharedMemorySize, SMEM_TOTAL);

    // 3 no-op launches: aim ncu capture (launch idx 3) at rnn_main
    for (int i = 0; i < 3; i++) knop<<<1, 32>>>();

    rnn_main<<<GRID, TPB, SMEM_TOTAL>>>(input, noise, wi, si, wrec, bias,
                                        wim, wrm, h0, traj);
    rnn_out<<<(B_ * T_) / 8, 256>>>(traj, wo, so, wom, out);
}